// round 15
// baseline (speedup 1.0000x reference)
#include <cuda_runtime.h>
#include <cstdint>

#define BB 64
#define TT 2000
#define QD 1024
#define MD 512
#define AD 128
#define NF 32
#define KW 31

#define TTILE 128
#define KC 32
#define ASTR 36    // (36*r + c)%32 = (4r+c)%32 bijective over r0..7,c0..3 -> conflict-free frags
#define BSTR 136   // (136*k + n)%32 = (8k+n)%32 bijective over k0..3,n0..7
#define ASZ (TTILE * ASTR)   // 4608 floats per buffer
#define BSZ (KC * BSTR)      // 4352 floats per buffer
#define BOFF (2 * ASZ)       // 9216

// scratch for processed query (no allocation allowed)
__device__ float g_pq[BB * AD];

__device__ __forceinline__ float fast_tanh(float x) {
    x = fminf(15.0f, fmaxf(-15.0f, x));
    float e = __expf(2.0f * x);
    return (e - 1.0f) * __frcp_rn(e + 1.0f);
}

__device__ __forceinline__ void cpa16(uint32_t s, const void* g, bool valid) {
    asm volatile("cp.async.cg.shared.global [%0], [%1], 16, %2;"
                 :: "r"(s), "l"(g), "r"(valid ? 16 : 0));
}

__device__ __forceinline__ void mma8(float& c0, float& c1, float& c2, float& c3,
                                     unsigned a0, unsigned a1, unsigned a2, unsigned a3,
                                     unsigned b0, unsigned b1) {
    asm volatile(
        "mma.sync.aligned.m16n8k8.row.col.f32.tf32.tf32.f32 "
        "{%0,%1,%2,%3}, {%4,%5,%6,%7}, {%8,%9}, {%0,%1,%2,%3};"
        : "+f"(c0), "+f"(c1), "+f"(c2), "+f"(c3)
        : "r"(a0), "r"(a1), "r"(a2), "r"(a3), "r"(b0), "r"(b1));
}

// one K=8 mma step over the full 128x128 tile for this warp
__device__ __forceinline__ void mma_ks(const float* Ab, const float* Bb, int ks,
                                       int wm, int wn, int g, int j,
                                       float acc[4][4][4]) {
    unsigned af[4][4];
#pragma unroll
    for (int mt = 0; mt < 4; mt++) {
        int r0 = wm * 64 + mt * 16 + g;
        int c0 = ks * 8 + j;
        af[mt][0] = __float_as_uint(Ab[r0 * ASTR + c0]);
        af[mt][1] = __float_as_uint(Ab[(r0 + 8) * ASTR + c0]);
        af[mt][2] = __float_as_uint(Ab[r0 * ASTR + c0 + 4]);
        af[mt][3] = __float_as_uint(Ab[(r0 + 8) * ASTR + c0 + 4]);
    }
#pragma unroll
    for (int nt = 0; nt < 4; nt++) {
        int nb = wn * 32 + nt * 8;
        unsigned b0 = __float_as_uint(Bb[(ks * 8 + j) * BSTR + nb + g]);
        unsigned b1 = __float_as_uint(Bb[(ks * 8 + j + 4) * BSTR + nb + g]);
#pragma unroll
        for (int mt = 0; mt < 4; mt++)
            mma8(acc[mt][nt][0], acc[mt][nt][1], acc[mt][nt][2], acc[mt][nt][3],
                 af[mt][0], af[mt][1], af[mt][2], af[mt][3], b0, b1);
    }
}

// one K=1 SIMT FFMA step over the same fragment ownership (fma pipe)
__device__ __forceinline__ void simt_k(const float* Ab, const float* Bb, int k,
                                       int wm, int wn, int g, int j,
                                       float acc[4][4][4]) {
    float a_[8];
#pragma unroll
    for (int mt = 0; mt < 4; mt++) {
        int r0 = wm * 64 + mt * 16 + g;
        a_[2 * mt]     = Ab[r0 * ASTR + k];
        a_[2 * mt + 1] = Ab[(r0 + 8) * ASTR + k];
    }
    float2 b_[4];
#pragma unroll
    for (int nt = 0; nt < 4; nt++)
        b_[nt] = *(const float2*)&Bb[k * BSTR + wn * 32 + nt * 8 + 2 * j];
#pragma unroll
    for (int mt = 0; mt < 4; mt++)
#pragma unroll
        for (int nt = 0; nt < 4; nt++) {
            acc[mt][nt][0] += a_[2 * mt]     * b_[nt].x;
            acc[mt][nt][1] += a_[2 * mt]     * b_[nt].y;
            acc[mt][nt][2] += a_[2 * mt + 1] * b_[nt].x;
            acc[mt][nt][3] += a_[2 * mt + 1] * b_[nt].y;
        }
}

// ---------------- Kernel 1: pq = tanh(query @ Wq), zero context --------------
__global__ void __launch_bounds__(1024, 1)
k_pq(const float* __restrict__ q, const float* __restrict__ Wq,
     float* __restrict__ ctx) {
    __shared__ float qs[QD];
    __shared__ float part[8][AD];
    const int b = blockIdx.x, tid = threadIdx.x;
    for (int i = tid; i < QD; i += 1024) qs[i] = q[b * QD + i];
    if (tid < MD) ctx[b * MD + tid] = 0.0f;
    __syncthreads();
    const int a = tid & 127, ks = tid >> 7;
    const float* wp = Wq + (ks * 128) * AD + a;
    const float* qp = qs + ks * 128;
    float acc = 0.0f;
#pragma unroll 16
    for (int k = 0; k < 128; k++) acc += qp[k] * wp[k * AD];
    part[ks][a] = acc;
    __syncthreads();
    if (tid < AD) {
        float s = 0.0f;
#pragma unroll
        for (int i = 0; i < 8; i++) s += part[i][tid];
        g_pq[b * AD + tid] = fast_tanh(s);
    }
}

// ---------------- Kernel 2: fused conv + loc GEMM + pm GEMM + energies --------
// grid: (16 t-tiles, 64 b), 256 threads (8 warps: 2 M x 4 N)
__global__ void __launch_bounds__(256, 1)
k_energies(const float* __restrict__ mem, const float* __restrict__ awc,
           const float* __restrict__ Wm, const float* __restrict__ ck,
           const float* __restrict__ Wloc, const float* __restrict__ Vv,
           float* __restrict__ ener) {
    extern __shared__ float sm[];
    float* As   = sm;
    float* Bs   = sm + BOFF;
    float* awcs = sm + 17920;
    float* pqs  = sm + 18240;
    float* Vs   = sm + 18368;
    float* ered = sm + 18496;

    const int b  = blockIdx.y;
    const int t0 = blockIdx.x * TTILE;
    const int tid = threadIdx.x;
    const int lane = tid & 31, w = tid >> 5;
    const int wm = w >> 2, wn = w & 3;
    const int g = lane >> 2, j = lane & 3;

    const uint32_t smbase = (uint32_t)__cvta_generic_to_shared(sm);

    const int ar = tid >> 3, ac = (tid & 7) * 4;
    const int kr = tid >> 5, kc = (tid & 31) * 4;
    const float* asrc0 = mem + ((size_t)(b * TT + t0 + ar)) * MD + ac;
    const float* bsrc0 = Wm + kr * AD + kc;
    const uint32_t adst0 = smbase + (uint32_t)(ar * ASTR + ac) * 4u;
    const uint32_t bdst0 = smbase + (uint32_t)(BOFF + kr * BSTR + kc) * 4u;

    // ---- prologue: issue chunk 0 -> buffer 0 ----
#pragma unroll
    for (int p = 0; p < 4; p++) {
        bool v = (t0 + ar + p * 32) < TT;
        cpa16(adst0 + (uint32_t)(p * 32 * ASTR) * 4u, asrc0 + (size_t)p * 32 * MD, v);
    }
#pragma unroll
    for (int p = 0; p < 4; p++)
        cpa16(bdst0 + (uint32_t)(p * 8 * BSTR) * 4u, bsrc0 + p * 8 * AD, true);
    asm volatile("cp.async.commit_group;" ::: "memory");

    // ---- setup: pq, V, awc halo tile ----
    if (tid < AD) { pqs[tid] = g_pq[b * AD + tid]; Vs[tid] = Vv[tid]; }
    for (int i = tid; i < 2 * 160; i += 256) {
        int c = i / 160, tl = i % 160;
        int t = t0 - 15 + tl;
        awcs[i] = (t >= 0 && t < TT) ? awc[(b * 2 + c) * TT + t] : 0.0f;
    }
    __syncthreads();

    // ---- phase 1: conv -> As buf1, Wloc -> Bs buf1 (raw fp32) ----
    {
        float* A1 = As + ASZ;
        float* B1 = Bs + BSZ;
        for (int i = tid; i < TTILE * NF; i += 256) {
            int tl = i >> 5, f = i & 31;
            float acc = 0.0f;
#pragma unroll
            for (int k = 0; k < KW; k++) {
                acc += awcs[tl + k]       * ck[(k * 2 + 0) * NF + f];
                acc += awcs[160 + tl + k] * ck[(k * 2 + 1) * NF + f];
            }
            A1[tl * ASTR + f] = acc;
        }
        for (int i = tid; i < NF * AD; i += 256) {
            int f = i >> 7, a = i & 127;
            B1[f * BSTR + a] = Wloc[i];
        }
    }
    __syncthreads();

    // ---- phase 2: loc GEMM (K=32) from buf1 ----
    float locf[4][4][4];
#pragma unroll
    for (int mt = 0; mt < 4; mt++)
#pragma unroll
        for (int nt = 0; nt < 4; nt++)
#pragma unroll
            for (int r = 0; r < 4; r++) locf[mt][nt][r] = 0.0f;
    {
        const float* Ab = As + ASZ;
        const float* Bb = Bs + BSZ;
#pragma unroll
        for (int ks = 0; ks < 4; ks++)
            mma_ks(Ab, Bb, ks, wm, wn, g, j, locf);
    }
#pragma unroll
    for (int mt = 0; mt < 4; mt++)
#pragma unroll
        for (int nt = 0; nt < 4; nt++) {
            int col0 = wn * 32 + nt * 8 + 2 * j;
            float p0 = pqs[col0], p1 = pqs[col0 + 1];
            locf[mt][nt][0] = fast_tanh(locf[mt][nt][0]) + p0;
            locf[mt][nt][1] = fast_tanh(locf[mt][nt][1]) + p1;
            locf[mt][nt][2] = fast_tanh(locf[mt][nt][2]) + p0;
            locf[mt][nt][3] = fast_tanh(locf[mt][nt][3]) + p1;
        }

    // ---- phase 3: pm GEMM, 16 K=32 chunks; HMMA+FFMA pipe split -------------
    float acc[4][4][4];
#pragma unroll
    for (int mt = 0; mt < 4; mt++)
#pragma unroll
        for (int nt = 0; nt < 4; nt++)
#pragma unroll
            for (int r = 0; r < 4; r++) acc[mt][nt][r] = 0.0f;

    for (int it = 0; it < 16; it++) {
        asm volatile("cp.async.wait_group 0;" ::: "memory");
        __syncthreads();
        if (it < 15) {
            const int nb = (it + 1) & 1;
            const int k0 = (it + 1) * KC;
#pragma unroll
            for (int p = 0; p < 4; p++) {
                bool v = (t0 + ar + p * 32) < TT;
                cpa16(adst0 + (uint32_t)(nb * ASZ + p * 32 * ASTR) * 4u,
                      asrc0 + k0 + (size_t)p * 32 * MD, v);
            }
#pragma unroll
            for (int p = 0; p < 4; p++)
                cpa16(bdst0 + (uint32_t)(nb * BSZ + p * 8 * BSTR) * 4u,
                      bsrc0 + k0 * AD + p * 8 * AD, true);
            asm volatile("cp.async.commit_group;" ::: "memory");
        }
        const float* Ab = As + (it & 1) * ASZ;
        const float* Bb = Bs + (it & 1) * BSZ;
        const bool typeB = ((it % 3) == 2);   // chunks 2,5,8,11,14
        if (!typeB) {
            // mma on k 0..23, SIMT FFMA on k 24..31
            mma_ks(Ab, Bb, 0, wm, wn, g, j, acc);
            mma_ks(Ab, Bb, 1, wm, wn, g, j, acc);
            mma_ks(Ab, Bb, 2, wm, wn, g, j, acc);
#pragma unroll
            for (int k = 24; k < 32; k++)
                simt_k(Ab, Bb, k, wm, wn, g, j, acc);
        } else {
            // mma on k 0..15, SIMT FFMA on k 16..31
            mma_ks(Ab, Bb, 0, wm, wn, g, j, acc);
            mma_ks(Ab, Bb, 1, wm, wn, g, j, acc);
#pragma unroll
            for (int k = 16; k < 32; k++)
                simt_k(Ab, Bb, k, wm, wn, g, j, acc);
        }
    }

    // ---- epilogue: e[t] = sum_a V[a] * tanh(tanh(loc)+pq + tanh(pm)) ----
#pragma unroll
    for (int mt = 0; mt < 4; mt++) {
        float p0 = 0.0f, p1 = 0.0f;
#pragma unroll
        for (int nt = 0; nt < 4; nt++) {
            int col0 = wn * 32 + nt * 8 + 2 * j;
            float v0 = Vs[col0], v1 = Vs[col0 + 1];
            p0 += v0 * fast_tanh(locf[mt][nt][0] + fast_tanh(acc[mt][nt][0]));
            p0 += v1 * fast_tanh(locf[mt][nt][1] + fast_tanh(acc[mt][nt][1]));
            p1 += v0 * fast_tanh(locf[mt][nt][2] + fast_tanh(acc[mt][nt][2]));
            p1 += v1 * fast_tanh(locf[mt][nt][3] + fast_tanh(acc[mt][nt][3]));
        }
        p0 += __shfl_xor_sync(0xffffffffu, p0, 1);
        p0 += __shfl_xor_sync(0xffffffffu, p0, 2);
        p1 += __shfl_xor_sync(0xffffffffu, p1, 1);
        p1 += __shfl_xor_sync(0xffffffffu, p1, 2);
        if (j == 0) {
            int r = wm * 64 + mt * 16 + g;
            ered[wn * 128 + r] = p0;
            ered[wn * 128 + r + 8] = p1;
        }
    }
    __syncthreads();
    if (tid < TTILE) {
        float e = ered[tid] + ered[128 + tid] + ered[256 + tid] + ered[384 + tid];
        int t = t0 + tid;
        if (t < TT) ener[b * TT + t] = e;
    }
}

// ---------------- Kernel 3: softmax over T per batch row ---------------------
__global__ void k_softmax(float* __restrict__ wts) {
    __shared__ float red[256];
    const int b = blockIdx.x, tid = threadIdx.x;
    float* e = wts + b * TT;
    float v[8];
    float mx = -1e30f;
#pragma unroll
    for (int i = 0; i < 8; i++) {
        int t = tid + i * 256;
        v[i] = (t < TT) ? e[t] : -1e30f;
        mx = fmaxf(mx, v[i]);
    }
    red[tid] = mx; __syncthreads();
    for (int s = 128; s > 0; s >>= 1) {
        if (tid < s) red[tid] = fmaxf(red[tid], red[tid + s]);
        __syncthreads();
    }
    mx = red[0]; __syncthreads();
    float sum = 0.0f;
#pragma unroll
    for (int i = 0; i < 8; i++) {
        int t = tid + i * 256;
        v[i] = (t < TT) ? __expf(v[i] - mx) : 0.0f;
        sum += v[i];
    }
    red[tid] = sum; __syncthreads();
    for (int s = 128; s > 0; s >>= 1) {
        if (tid < s) red[tid] += red[tid + s];
        __syncthreads();
    }
    float inv = 1.0f / red[0];
#pragma unroll
    for (int i = 0; i < 8; i++) {
        int t = tid + i * 256;
        if (t < TT) e[t] = v[i] * inv;
    }
}

// ---------------- Kernel 4: context = w @ memory (memory-bound) --------------
__global__ void k_context(const float* __restrict__ mem, const float* __restrict__ wts,
                          float* __restrict__ ctx) {
    __shared__ float ws[200];
    const int b = blockIdx.y, tid = threadIdx.x;
    const int tstart = blockIdx.x * 200;
    if (tid < 200) ws[tid] = wts[b * TT + tstart + tid];
    __syncthreads();
    const int d = (tid & 127) * 4;
    const int r0 = tid >> 7;
    const float* mp = mem + ((size_t)(b * TT + tstart + r0)) * MD + d;
    float ax = 0.f, ay = 0.f, az = 0.f, aw = 0.f;
#pragma unroll 4
    for (int t = 0; t < 200; t += 2) {
        float4 m = *(const float4*)(mp + (size_t)t * MD);
        float wv = ws[t + r0];
        ax += wv * m.x; ay += wv * m.y; az += wv * m.z; aw += wv * m.w;
    }
    atomicAdd(&ctx[b * MD + d + 0], ax);
    atomicAdd(&ctx[b * MD + d + 1], ay);
    atomicAdd(&ctx[b * MD + d + 2], az);
    atomicAdd(&ctx[b * MD + d + 3], aw);
}

// ---------------- launch -----------------------------------------------------
extern "C" void kernel_launch(void* const* d_in, const int* in_sizes, int n_in,
                              void* d_out, int out_size) {
    const float* q    = (const float*)d_in[0];
    const float* mem  = (const float*)d_in[1];
    const float* awc  = (const float*)d_in[2];
    const float* Wq   = (const float*)d_in[3];
    const float* Wm   = (const float*)d_in[4];
    const float* ck   = (const float*)d_in[5];
    const float* Wloc = (const float*)d_in[6];
    const float* V    = (const float*)d_in[7];

    float* ctx = (float*)d_out;            // [64, 512]
    float* wts = (float*)d_out + BB * MD;  // [64, 2000]

    cudaFuncSetAttribute(k_energies, cudaFuncAttributeMaxDynamicSharedMemorySize, 19008 * 4);

    k_pq<<<BB, 1024>>>(q, Wq, ctx);
    dim3 gE(16, BB);
    k_energies<<<gE, 256, 19008 * 4>>>(mem, awc, Wm, ck, Wloc, V, wts);
    k_softmax<<<BB, 256>>>(wts);
    dim3 gC(10, BB);
    k_context<<<gC, 256>>>(mem, wts, ctx);
}

// round 16
// speedup vs baseline: 1.8790x; 1.8790x over previous
#include <cuda_runtime.h>
#include <cstdint>

#define BB 64
#define TT 2000
#define QD 1024
#define MD 512
#define AD 128
#define NF 32
#define KW 31

#define TTILE 128
#define KC 32
#define ASTR 36    // (36*r + c)%32 = (4r+c)%32 bijective over r0..7,c0..3 -> conflict-free frags
#define BSTR 136   // (136*k + n)%32 = (8k+n)%32 bijective over k0..3,n0..7
#define ASZ (TTILE * ASTR)   // 4608 floats per buffer
#define BSZ (KC * BSTR)      // 4352 floats per buffer
#define BOFF (2 * ASZ)       // 9216

// device scratch (no allocation allowed)
__device__ float g_pq[BB * AD];
__device__ float g_ener[BB * TT];

__device__ __forceinline__ float fast_tanh(float x) {
    x = fminf(15.0f, fmaxf(-15.0f, x));
    float e = __expf(2.0f * x);
    return (e - 1.0f) * __frcp_rn(e + 1.0f);
}

__device__ __forceinline__ void cpa16(uint32_t s, const void* g, bool valid) {
    asm volatile("cp.async.cg.shared.global [%0], [%1], 16, %2;"
                 :: "r"(s), "l"(g), "r"(valid ? 16 : 0));
}

__device__ __forceinline__ void mma8(float& c0, float& c1, float& c2, float& c3,
                                     unsigned a0, unsigned a1, unsigned a2, unsigned a3,
                                     unsigned b0, unsigned b1) {
    asm volatile(
        "mma.sync.aligned.m16n8k8.row.col.f32.tf32.tf32.f32 "
        "{%0,%1,%2,%3}, {%4,%5,%6,%7}, {%8,%9}, {%0,%1,%2,%3};"
        : "+f"(c0), "+f"(c1), "+f"(c2), "+f"(c3)
        : "r"(a0), "r"(a1), "r"(a2), "r"(a3), "r"(b0), "r"(b1));
}

// one K=8 mma step over the full 128x128 tile for this warp
__device__ __forceinline__ void mma_ks(const float* Ab, const float* Bb, int ks,
                                       int wm, int wn, int g, int j,
                                       float acc[4][4][4]) {
    unsigned af[4][4];
#pragma unroll
    for (int mt = 0; mt < 4; mt++) {
        int r0 = wm * 64 + mt * 16 + g;
        int c0 = ks * 8 + j;
        af[mt][0] = __float_as_uint(Ab[r0 * ASTR + c0]);
        af[mt][1] = __float_as_uint(Ab[(r0 + 8) * ASTR + c0]);
        af[mt][2] = __float_as_uint(Ab[r0 * ASTR + c0 + 4]);
        af[mt][3] = __float_as_uint(Ab[(r0 + 8) * ASTR + c0 + 4]);
    }
#pragma unroll
    for (int nt = 0; nt < 4; nt++) {
        int nb = wn * 32 + nt * 8;
        unsigned b0 = __float_as_uint(Bb[(ks * 8 + j) * BSTR + nb + g]);
        unsigned b1 = __float_as_uint(Bb[(ks * 8 + j + 4) * BSTR + nb + g]);
#pragma unroll
        for (int mt = 0; mt < 4; mt++)
            mma8(acc[mt][nt][0], acc[mt][nt][1], acc[mt][nt][2], acc[mt][nt][3],
                 af[mt][0], af[mt][1], af[mt][2], af[mt][3], b0, b1);
    }
}

// ---------------- Kernel 1: pq = tanh(query @ Wq), zero context --------------
__global__ void __launch_bounds__(1024, 1)
k_pq(const float* __restrict__ q, const float* __restrict__ Wq,
     float* __restrict__ ctx) {
    __shared__ float qs[QD];
    __shared__ float part[8][AD];
    const int b = blockIdx.x, tid = threadIdx.x;
    for (int i = tid; i < QD; i += 1024) qs[i] = q[b * QD + i];
    if (tid < MD) ctx[b * MD + tid] = 0.0f;
    __syncthreads();
    const int a = tid & 127, ks = tid >> 7;
    const float* wp = Wq + (ks * 128) * AD + a;
    const float* qp = qs + ks * 128;
    float acc = 0.0f;
#pragma unroll 16
    for (int k = 0; k < 128; k++) acc += qp[k] * wp[k * AD];
    part[ks][a] = acc;
    __syncthreads();
    if (tid < AD) {
        float s = 0.0f;
#pragma unroll
        for (int i = 0; i < 8; i++) s += part[i][tid];
        g_pq[b * AD + tid] = fast_tanh(s);
    }
}

// ---------------- Kernel 2: fused conv + loc GEMM + pm GEMM + energies --------
// grid: (16 t-tiles, 64 b), 256 threads (8 warps: 2 M x 4 N)
__global__ void __launch_bounds__(256, 1)
k_energies(const float* __restrict__ mem, const float* __restrict__ awc,
           const float* __restrict__ Wm, const float* __restrict__ ck,
           const float* __restrict__ Wloc, const float* __restrict__ Vv) {
    extern __shared__ float sm[];
    float* As   = sm;
    float* Bs   = sm + BOFF;
    float* awcs = sm + 17920;
    float* pqs  = sm + 18240;
    float* Vs   = sm + 18368;
    float* ered = sm + 18496;

    const int b  = blockIdx.y;
    const int t0 = blockIdx.x * TTILE;
    const int tid = threadIdx.x;
    const int lane = tid & 31, w = tid >> 5;
    const int wm = w >> 2, wn = w & 3;
    const int g = lane >> 2, j = lane & 3;

    const uint32_t smbase = (uint32_t)__cvta_generic_to_shared(sm);

    const int ar = tid >> 3, ac = (tid & 7) * 4;
    const int kr = tid >> 5, kc = (tid & 31) * 4;
    const float* asrc0 = mem + ((size_t)(b * TT + t0 + ar)) * MD + ac;
    const float* bsrc0 = Wm + kr * AD + kc;
    const uint32_t adst0 = smbase + (uint32_t)(ar * ASTR + ac) * 4u;
    const uint32_t bdst0 = smbase + (uint32_t)(BOFF + kr * BSTR + kc) * 4u;

    // ---- prologue: issue chunk 0 -> buffer 0 ----
#pragma unroll
    for (int p = 0; p < 4; p++) {
        bool v = (t0 + ar + p * 32) < TT;
        cpa16(adst0 + (uint32_t)(p * 32 * ASTR) * 4u, asrc0 + (size_t)p * 32 * MD, v);
    }
#pragma unroll
    for (int p = 0; p < 4; p++)
        cpa16(bdst0 + (uint32_t)(p * 8 * BSTR) * 4u, bsrc0 + p * 8 * AD, true);
    asm volatile("cp.async.commit_group;" ::: "memory");

    // ---- setup: pq, V, awc halo tile ----
    if (tid < AD) { pqs[tid] = g_pq[b * AD + tid]; Vs[tid] = Vv[tid]; }
    for (int i = tid; i < 2 * 160; i += 256) {
        int c = i / 160, tl = i % 160;
        int t = t0 - 15 + tl;
        awcs[i] = (t >= 0 && t < TT) ? awc[(b * 2 + c) * TT + t] : 0.0f;
    }
    __syncthreads();

    // ---- phase 1: conv -> As buf1, Wloc -> Bs buf1 (raw fp32) ----
    {
        float* A1 = As + ASZ;
        float* B1 = Bs + BSZ;
        for (int i = tid; i < TTILE * NF; i += 256) {
            int tl = i >> 5, f = i & 31;
            float acc = 0.0f;
#pragma unroll
            for (int k = 0; k < KW; k++) {
                acc += awcs[tl + k]       * ck[(k * 2 + 0) * NF + f];
                acc += awcs[160 + tl + k] * ck[(k * 2 + 1) * NF + f];
            }
            A1[tl * ASTR + f] = acc;
        }
        for (int i = tid; i < NF * AD; i += 256) {
            int f = i >> 7, a = i & 127;
            B1[f * BSTR + a] = Wloc[i];
        }
    }
    __syncthreads();

    // ---- phase 2: loc GEMM (K=32) from buf1 ----
    float locf[4][4][4];
#pragma unroll
    for (int mt = 0; mt < 4; mt++)
#pragma unroll
        for (int nt = 0; nt < 4; nt++)
#pragma unroll
            for (int r = 0; r < 4; r++) locf[mt][nt][r] = 0.0f;
    {
        const float* Ab = As + ASZ;
        const float* Bb = Bs + BSZ;
#pragma unroll
        for (int ks = 0; ks < 4; ks++)
            mma_ks(Ab, Bb, ks, wm, wn, g, j, locf);
    }
#pragma unroll
    for (int mt = 0; mt < 4; mt++)
#pragma unroll
        for (int nt = 0; nt < 4; nt++) {
            int col0 = wn * 32 + nt * 8 + 2 * j;
            float p0 = pqs[col0], p1 = pqs[col0 + 1];
            locf[mt][nt][0] = fast_tanh(locf[mt][nt][0]) + p0;
            locf[mt][nt][1] = fast_tanh(locf[mt][nt][1]) + p1;
            locf[mt][nt][2] = fast_tanh(locf[mt][nt][2]) + p0;
            locf[mt][nt][3] = fast_tanh(locf[mt][nt][3]) + p1;
        }

    // ---- phase 3: pm GEMM, 16 K=32 chunks, cp.async double-buffer ----
    float acc[4][4][4];
#pragma unroll
    for (int mt = 0; mt < 4; mt++)
#pragma unroll
        for (int nt = 0; nt < 4; nt++)
#pragma unroll
            for (int r = 0; r < 4; r++) acc[mt][nt][r] = 0.0f;

    for (int it = 0; it < 16; it++) {
        asm volatile("cp.async.wait_group 0;" ::: "memory");
        __syncthreads();
        if (it < 15) {
            const int nb = (it + 1) & 1;
            const int k0 = (it + 1) * KC;
#pragma unroll
            for (int p = 0; p < 4; p++) {
                bool v = (t0 + ar + p * 32) < TT;
                cpa16(adst0 + (uint32_t)(nb * ASZ + p * 32 * ASTR) * 4u,
                      asrc0 + k0 + (size_t)p * 32 * MD, v);
            }
#pragma unroll
            for (int p = 0; p < 4; p++)
                cpa16(bdst0 + (uint32_t)(nb * BSZ + p * 8 * BSTR) * 4u,
                      bsrc0 + k0 * AD + p * 8 * AD, true);
            asm volatile("cp.async.commit_group;" ::: "memory");
        }
        const float* Ab = As + (it & 1) * ASZ;
        const float* Bb = Bs + (it & 1) * BSZ;
#pragma unroll
        for (int ks = 0; ks < 4; ks++)
            mma_ks(Ab, Bb, ks, wm, wn, g, j, acc);
    }

    // ---- epilogue: e[t] = sum_a V[a] * tanh(tanh(loc)+pq + tanh(pm)) ----
#pragma unroll
    for (int mt = 0; mt < 4; mt++) {
        float p0 = 0.0f, p1 = 0.0f;
#pragma unroll
        for (int nt = 0; nt < 4; nt++) {
            int col0 = wn * 32 + nt * 8 + 2 * j;
            float v0 = Vs[col0], v1 = Vs[col0 + 1];
            p0 += v0 * fast_tanh(locf[mt][nt][0] + fast_tanh(acc[mt][nt][0]));
            p0 += v1 * fast_tanh(locf[mt][nt][1] + fast_tanh(acc[mt][nt][1]));
            p1 += v0 * fast_tanh(locf[mt][nt][2] + fast_tanh(acc[mt][nt][2]));
            p1 += v1 * fast_tanh(locf[mt][nt][3] + fast_tanh(acc[mt][nt][3]));
        }
        p0 += __shfl_xor_sync(0xffffffffu, p0, 1);
        p0 += __shfl_xor_sync(0xffffffffu, p0, 2);
        p1 += __shfl_xor_sync(0xffffffffu, p1, 1);
        p1 += __shfl_xor_sync(0xffffffffu, p1, 2);
        if (j == 0) {
            int r = wm * 64 + mt * 16 + g;
            ered[wn * 128 + r] = p0;
            ered[wn * 128 + r + 8] = p1;
        }
    }
    __syncthreads();
    if (tid < TTILE) {
        float e = ered[tid] + ered[128 + tid] + ered[256 + tid] + ered[384 + tid];
        int t = t0 + tid;
        if (t < TT) g_ener[b * TT + t] = e;
    }
}

// ---------------- Kernel 3: fused softmax + context + weights ----------------
// grid (10 t-chunks, 64 b), 512 threads. Each CTA: full-row softmax stats
// (L2-hot redundant reduce), writes its 200-weight chunk, accumulates context.
__global__ void __launch_bounds__(512, 1)
k_ctx(const float* __restrict__ mem, float* __restrict__ wts,
      float* __restrict__ ctx) {
    __shared__ float red[512];
    __shared__ float ws[200];
    const int b = blockIdx.y, tid = threadIdx.x;
    const int tstart = blockIdx.x * 200;
    const float* e = g_ener + b * TT;

    // row max
    float mx = -1e30f;
#pragma unroll
    for (int i = 0; i < 4; i++) {
        int t = tid + i * 512;
        if (t < TT) mx = fmaxf(mx, e[t]);
    }
    red[tid] = mx; __syncthreads();
    for (int s = 256; s > 0; s >>= 1) {
        if (tid < s) red[tid] = fmaxf(red[tid], red[tid + s]);
        __syncthreads();
    }
    mx = red[0]; __syncthreads();
    // row sum of exp
    float sum = 0.0f;
#pragma unroll
    for (int i = 0; i < 4; i++) {
        int t = tid + i * 512;
        if (t < TT) sum += __expf(e[t] - mx);
    }
    red[tid] = sum; __syncthreads();
    for (int s = 256; s > 0; s >>= 1) {
        if (tid < s) red[tid] += red[tid + s];
        __syncthreads();
    }
    const float invL = 1.0f / red[0];

    // this chunk's normalized weights -> smem + output
    if (tid < 200) {
        float wv = __expf(e[tstart + tid] - mx) * invL;
        ws[tid] = wv;
        wts[b * TT + tstart + tid] = wv;
    }
    __syncthreads();

    // context: 128 col-groups x 4 rows in flight
    const int d = (tid & 127) * 4;
    const int r0 = tid >> 7;   // 0..3
    const float* mp = mem + ((size_t)(b * TT + tstart + r0)) * MD + d;
    float ax = 0.f, ay = 0.f, az = 0.f, aw = 0.f;
#pragma unroll 5
    for (int t = 0; t < 200; t += 4) {
        float4 m = *(const float4*)(mp + (size_t)t * MD);
        float wv = ws[t + r0];
        ax += wv * m.x; ay += wv * m.y; az += wv * m.z; aw += wv * m.w;
    }
    atomicAdd(&ctx[b * MD + d + 0], ax);
    atomicAdd(&ctx[b * MD + d + 1], ay);
    atomicAdd(&ctx[b * MD + d + 2], az);
    atomicAdd(&ctx[b * MD + d + 3], aw);
}

// ---------------- launch -----------------------------------------------------
extern "C" void kernel_launch(void* const* d_in, const int* in_sizes, int n_in,
                              void* d_out, int out_size) {
    const float* q    = (const float*)d_in[0];
    const float* mem  = (const float*)d_in[1];
    const float* awc  = (const float*)d_in[2];
    const float* Wq   = (const float*)d_in[3];
    const float* Wm   = (const float*)d_in[4];
    const float* ck   = (const float*)d_in[5];
    const float* Wloc = (const float*)d_in[6];
    const float* V    = (const float*)d_in[7];

    float* ctx = (float*)d_out;            // [64, 512]
    float* wts = (float*)d_out + BB * MD;  // [64, 2000]

    cudaFuncSetAttribute(k_energies, cudaFuncAttributeMaxDynamicSharedMemorySize, 19008 * 4);

    k_pq<<<BB, 1024>>>(q, Wq, ctx);
    dim3 gE(16, BB);
    k_energies<<<gE, 256, 19008 * 4>>>(mem, awc, Wm, ck, Wloc, V);
    dim3 gC(10, BB);
    k_ctx<<<gC, 512>>>(mem, wts, ctx);
}